// round 1
// baseline (speedup 1.0000x reference)
#include <cuda_runtime.h>

// Problem constants (fixed by the reference setup)
#define KK    8
#define RR    200000
#define CIN   32
#define COUT  32
#define NOUT  400000
#define TILE  256

// ---------------------------------------------------------------------------
// Kernel 1: initialize output to bias (d_out is poisoned to 0xAA each run)
// ---------------------------------------------------------------------------
__global__ void init_out_kernel(float* __restrict__ out,
                                const float* __restrict__ bias) {
    int idx = blockIdx.x * blockDim.x + threadIdx.x;
    const int total4 = NOUT * COUT / 4;   // 3.2M float4
    if (idx < total4) {
        int c = (idx & 7) * 4;            // channel base (COUT=32 -> 8 float4 per row)
        float4 v = make_float4(bias[c], bias[c + 1], bias[c + 2], bias[c + 3]);
        reinterpret_cast<float4*>(out)[idx] = v;
    }
}

// ---------------------------------------------------------------------------
// Kernel 2: gather -> 32x32 GEMV per rule -> scatter-add
//   blockIdx.y = k (weight offset), blockIdx.x = rule tile
//   256 threads = 8 warps. Thread's lane = output channel.
//   Weight W[k][c][lane] lives in 32 registers per thread.
// ---------------------------------------------------------------------------
__global__ void __launch_bounds__(256)
scatter_conv_kernel(const float* __restrict__ feats,    // [N_IN, 32]
                    const float* __restrict__ weight,   // [K, 1, 32, 32]
                    const int*   __restrict__ rules_in, // [K, R]
                    const int*   __restrict__ rules_out,// [K, R]
                    float*       __restrict__ out)      // [NOUT, 32]
{
    __shared__ float sIn[TILE][CIN];   // gathered input rows (32 KB)
    __shared__ int   sRin[TILE];
    __shared__ int   sRout[TILE];

    const int k    = blockIdx.y;
    const int tid  = threadIdx.x;
    const int lane = tid & 31;
    const int warp = tid >> 5;
    const int base = blockIdx.x * TILE;
    const int nrules = min(TILE, RR - base);

    // Per-thread weight column: W[k][c][lane], c = 0..31 (coalesced loads)
    float w[CIN];
    const float* wk = weight + (size_t)k * CIN * COUT;
    #pragma unroll
    for (int c = 0; c < CIN; c++) w[c] = __ldg(wk + c * COUT + lane);

    // Stage rule indices
    if (tid < nrules) {
        sRin[tid]  = rules_in [k * RR + base + tid];
        sRout[tid] = rules_out[k * RR + base + tid];
    }
    __syncthreads();

    // Gather: 8 threads per row load one float4 each -> full 128B line per row
    #pragma unroll
    for (int pass = 0; pass < TILE / 32; pass++) {
        int row = pass * 32 + (tid >> 3);
        if (row < nrules) {
            const float4* src =
                reinterpret_cast<const float4*>(feats + (size_t)sRin[row] * CIN);
            reinterpret_cast<float4*>(sIn[row])[tid & 7] = __ldg(src + (tid & 7));
        }
    }
    __syncthreads();

    // Compute + scatter: warp owns rows [warp*32, warp*32+32)
    for (int i = 0; i < TILE / 8; i++) {
        int row = warp * (TILE / 8) + i;
        if (row >= nrules) break;
        const float4* inr = reinterpret_cast<const float4*>(sIn[row]);
        float acc0 = 0.f, acc1 = 0.f;
        #pragma unroll
        for (int c4 = 0; c4 < CIN / 4; c4 += 2) {
            float4 v0 = inr[c4];
            float4 v1 = inr[c4 + 1];
            acc0 = fmaf(v0.x, w[4 * c4 + 0], acc0);
            acc0 = fmaf(v0.y, w[4 * c4 + 1], acc0);
            acc0 = fmaf(v0.z, w[4 * c4 + 2], acc0);
            acc0 = fmaf(v0.w, w[4 * c4 + 3], acc0);
            acc1 = fmaf(v1.x, w[4 * c4 + 4], acc1);
            acc1 = fmaf(v1.y, w[4 * c4 + 5], acc1);
            acc1 = fmaf(v1.z, w[4 * c4 + 6], acc1);
            acc1 = fmaf(v1.w, w[4 * c4 + 7], acc1);
        }
        // 32 lanes hit 32 consecutive floats = one 128B line -> coalesced RED
        atomicAdd(out + (size_t)sRout[row] * COUT + lane, acc0 + acc1);
    }
}

// ---------------------------------------------------------------------------
extern "C" void kernel_launch(void* const* d_in, const int* in_sizes, int n_in,
                              void* d_out, int out_size) {
    const float* feats  = (const float*)d_in[0];  // input_features [1.6M, 32] f32
    const float* weight = (const float*)d_in[1];  // weight [8,1,32,32] f32
    const float* bias   = (const float*)d_in[2];  // bias [32] f32
    const int*   rin    = (const int*)  d_in[3];  // rules_in [8, 200000] i32
    const int*   rout   = (const int*)  d_in[4];  // rules_out [8, 200000] i32
    float* out = (float*)d_out;                   // [400000, 32] f32

    const int total4 = NOUT * COUT / 4;
    init_out_kernel<<<(total4 + 255) / 256, 256>>>(out, bias);

    dim3 grid((RR + TILE - 1) / TILE, KK);
    scatter_conv_kernel<<<grid, 256>>>(feats, weight, rin, rout, out);
}

// round 3
// speedup vs baseline: 1.2047x; 1.2047x over previous
#include <cuda_runtime.h>
#include <cstdint>

// Problem constants (fixed by the reference setup)
#define KK    8
#define RR    200000
#define CIN   32
#define COUT  32
#define NOUT  400000
#define TILE  128          // rules per pipeline stage
#define TPB   1024         // rules per block (index preload granularity)

// ---------------------------------------------------------------------------
// Kernel 1: initialize output to bias (d_out is poisoned to 0xAA each run)
// ---------------------------------------------------------------------------
__global__ void init_out_kernel(float* __restrict__ out,
                                const float* __restrict__ bias) {
    int idx = blockIdx.x * blockDim.x + threadIdx.x;
    const int total4 = NOUT * COUT / 4;
    if (idx < total4) {
        int c = (idx & 7) * 4;
        float4 v = make_float4(bias[c], bias[c + 1], bias[c + 2], bias[c + 3]);
        reinterpret_cast<float4*>(out)[idx] = v;
    }
}

// ---------------------------------------------------------------------------
// Kernel 2: pipelined gather (cp.async) -> 32x32 GEMV -> coalesced scatter-RED
//   blockIdx.y = k, blockIdx.x = 1024-rule chunk
//   Double-buffered TILE=128 stages; weights in 32 regs; lane = out channel.
// ---------------------------------------------------------------------------
__global__ void __launch_bounds__(256, 4)
scatter_conv_kernel(const float* __restrict__ feats,    // [N_IN, 32]
                    const float* __restrict__ weight,   // [K, 1, 32, 32]
                    const int*   __restrict__ rules_in, // [K, R]
                    const int*   __restrict__ rules_out,// [K, R]
                    float*       __restrict__ out)      // [NOUT, 32]
{
    __shared__ float sIn[2][TILE][CIN];   // 2 x 16 KB staging
    __shared__ int   sRin[TPB];
    __shared__ int   sRout[TPB];

    const int k    = blockIdx.y;
    const int tid  = threadIdx.x;
    const int lane = tid & 31;
    const int warp = tid >> 5;
    const int base = blockIdx.x * TPB;
    const int nblk = min(TPB, RR - base);
    const int T    = (nblk + TILE - 1) / TILE;

    // Per-thread weight column: W[k][c][lane] (coalesced, once per block)
    float w[CIN];
    const float* wk = weight + (size_t)k * CIN * COUT;
    #pragma unroll
    for (int c = 0; c < CIN; c++) w[c] = __ldg(wk + c * COUT + lane);

    // Preload this block's rule indices (int4 vectorized; TPB/4 = 256)
    {
        const int4* rin4  = reinterpret_cast<const int4*>(rules_in  + k * RR + base);
        const int4* rout4 = reinterpret_cast<const int4*>(rules_out + k * RR + base);
        if (tid * 4 < nblk) {
            reinterpret_cast<int4*>(sRin)[tid]  = __ldg(rin4  + tid);
            reinterpret_cast<int4*>(sRout)[tid] = __ldg(rout4 + tid);
        }
    }
    __syncthreads();

    // Async gather of one tile into one buffer: 128 rows x 128 B,
    // 1024 x 16B chunks, 4 per thread; threads 0..7 cover row 0's line, etc.
    auto issue_gather = [&](int t, int buf) {
        const int trules = min(TILE, nblk - t * TILE);
        #pragma unroll
        for (int i = 0; i < 4; i++) {
            int chunk = tid + i * 256;
            int row   = chunk >> 3;
            int seg   = chunk & 7;
            if (row < trules) {
                const float* g = feats + (size_t)sRin[t * TILE + row] * CIN + seg * 4;
                uint32_t s = (uint32_t)__cvta_generic_to_shared(&sIn[buf][row][seg * 4]);
                asm volatile("cp.async.cg.shared.global [%0], [%1], 16;\n"
                             :: "r"(s), "l"(g));
            }
        }
    };

    issue_gather(0, 0);
    asm volatile("cp.async.commit_group;\n" ::: "memory");

    for (int t = 0; t < T; t++) {
        if (t + 1 < T) issue_gather(t + 1, (t + 1) & 1);
        asm volatile("cp.async.commit_group;\n" ::: "memory");
        asm volatile("cp.async.wait_group 1;\n" ::: "memory");  // tile t landed
        __syncthreads();

        const int trules = min(TILE, nblk - t * TILE);
        const int buf = t & 1;

        // 8 warps x 16 rules; lane = output channel; 1 coalesced RED per rule
        #pragma unroll 1
        for (int i = 0; i < TILE / 8; i++) {
            int row = warp * (TILE / 8) + i;
            if (row < trules) {
                const float4* inr = reinterpret_cast<const float4*>(sIn[buf][row]);
                float acc0 = 0.f, acc1 = 0.f, acc2 = 0.f, acc3 = 0.f;
                // batch 1: c = 0..15
                {
                    float4 v0 = inr[0], v1 = inr[1], v2 = inr[2], v3 = inr[3];
                    acc0 = fmaf(v0.x, w[0],  acc0); acc0 = fmaf(v0.y, w[1],  acc0);
                    acc0 = fmaf(v0.z, w[2],  acc0); acc0 = fmaf(v0.w, w[3],  acc0);
                    acc1 = fmaf(v1.x, w[4],  acc1); acc1 = fmaf(v1.y, w[5],  acc1);
                    acc1 = fmaf(v1.z, w[6],  acc1); acc1 = fmaf(v1.w, w[7],  acc1);
                    acc2 = fmaf(v2.x, w[8],  acc2); acc2 = fmaf(v2.y, w[9],  acc2);
                    acc2 = fmaf(v2.z, w[10], acc2); acc2 = fmaf(v2.w, w[11], acc2);
                    acc3 = fmaf(v3.x, w[12], acc3); acc3 = fmaf(v3.y, w[13], acc3);
                    acc3 = fmaf(v3.z, w[14], acc3); acc3 = fmaf(v3.w, w[15], acc3);
                }
                // batch 2: c = 16..31
                {
                    float4 v0 = inr[4], v1 = inr[5], v2 = inr[6], v3 = inr[7];
                    acc0 = fmaf(v0.x, w[16], acc0); acc0 = fmaf(v0.y, w[17], acc0);
                    acc0 = fmaf(v0.z, w[18], acc0); acc0 = fmaf(v0.w, w[19], acc0);
                    acc1 = fmaf(v1.x, w[20], acc1); acc1 = fmaf(v1.y, w[21], acc1);
                    acc1 = fmaf(v1.z, w[22], acc1); acc1 = fmaf(v1.w, w[23], acc1);
                    acc2 = fmaf(v2.x, w[24], acc2); acc2 = fmaf(v2.y, w[25], acc2);
                    acc2 = fmaf(v2.z, w[26], acc2); acc2 = fmaf(v2.w, w[27], acc2);
                    acc3 = fmaf(v3.x, w[28], acc3); acc3 = fmaf(v3.y, w[29], acc3);
                    acc3 = fmaf(v3.z, w[30], acc3); acc3 = fmaf(v3.w, w[31], acc3);
                }
                // 32 lanes -> 32 consecutive floats = one 128B line (cheap RED)
                atomicAdd(out + (size_t)sRout[t * TILE + row] * COUT + lane,
                          (acc0 + acc1) + (acc2 + acc3));
            }
        }
        __syncthreads();   // protect buf before gather(t+2) overwrites it
    }
}

// ---------------------------------------------------------------------------
extern "C" void kernel_launch(void* const* d_in, const int* in_sizes, int n_in,
                              void* d_out, int out_size) {
    const float* feats  = (const float*)d_in[0];
    const float* weight = (const float*)d_in[1];
    const float* bias   = (const float*)d_in[2];
    const int*   rin    = (const int*)  d_in[3];
    const int*   rout   = (const int*)  d_in[4];
    float* out = (float*)d_out;

    const int total4 = NOUT * COUT / 4;
    init_out_kernel<<<(total4 + 255) / 256, 256>>>(out, bias);

    dim3 grid((RR + TPB - 1) / TPB, KK);
    scatter_conv_kernel<<<grid, 256>>>(feats, weight, rin, rout, out);
}

// round 4
// speedup vs baseline: 1.2921x; 1.0725x over previous
#include <cuda_runtime.h>
#include <cstdint>

// Problem constants (fixed by the reference setup)
#define KK    8
#define RR    200000
#define CIN   32
#define COUT  32
#define NOUT  400000
#define TILE  128          // rules per pipeline stage
#define TPB   512          // rules per block
#define RPW   (TILE / 8)   // rules per warp per tile = 16
#define ASTRIDE 33         // padded accumulator stride (conflict-free)

// ---------------------------------------------------------------------------
// Kernel 1: initialize output to bias (d_out is poisoned to 0xAA each run)
// ---------------------------------------------------------------------------
__global__ void init_out_kernel(float* __restrict__ out,
                                const float* __restrict__ bias) {
    int idx = blockIdx.x * blockDim.x + threadIdx.x;
    const int total4 = NOUT * COUT / 4;
    if (idx < total4) {
        int c = (idx & 7) * 4;
        float4 v = make_float4(bias[c], bias[c + 1], bias[c + 2], bias[c + 3]);
        reinterpret_cast<float4*>(out)[idx] = v;
    }
}

// ---------------------------------------------------------------------------
// packed fp32x2 helpers (sm_103a dual-FP32 path; PTX-only)
// ---------------------------------------------------------------------------
__device__ __forceinline__ void fma2(uint64_t& d, uint64_t a, uint64_t b) {
    asm("fma.rn.f32x2 %0, %1, %2, %0;" : "+l"(d) : "l"(a), "l"(b));
}
__device__ __forceinline__ uint64_t add2(uint64_t a, uint64_t b) {
    uint64_t d;
    asm("add.rn.f32x2 %0, %1, %2;" : "=l"(d) : "l"(a), "l"(b));
    return d;
}
__device__ __forceinline__ uint64_t pack2(float lo, float hi) {
    uint64_t d;
    asm("mov.b64 %0, {%1, %2};" : "=l"(d) : "f"(lo), "f"(hi));
    return d;
}
__device__ __forceinline__ float unpack_sum(uint64_t a) {
    float lo, hi;
    asm("mov.b64 {%0, %1}, %2;" : "=f"(lo), "=f"(hi) : "l"(a));
    return lo + hi;
}
__device__ __forceinline__ void red4(float* addr, float a, float b, float c, float d) {
    asm volatile("red.global.add.v4.f32 [%0], {%1, %2, %3, %4};"
                 :: "l"(addr), "f"(a), "f"(b), "f"(c), "f"(d) : "memory");
}

// ---------------------------------------------------------------------------
// Kernel 2: cp.async pipelined gather -> f32x2 GEMV -> transposed v4 RED
// ---------------------------------------------------------------------------
__global__ void __launch_bounds__(256, 4)
scatter_conv_kernel(const float* __restrict__ feats,    // [N_IN, 32]
                    const float* __restrict__ weight,   // [K, 1, 32, 32]
                    const int*   __restrict__ rules_in, // [K, R]
                    const int*   __restrict__ rules_out,// [K, R]
                    float*       __restrict__ out)      // [NOUT, 32]
{
    __shared__ float sIn[2][TILE][CIN];        // 2 x 16 KB gather staging
    __shared__ float sAcc[TILE][ASTRIDE];      // per-warp acc transpose (16.9 KB)
    __shared__ int   sRin[TPB];
    __shared__ int   sRout[TPB];

    const int k    = blockIdx.y;
    const int tid  = threadIdx.x;
    const int lane = tid & 31;
    const int warp = tid >> 5;
    const int base = blockIdx.x * TPB;
    const int nblk = min(TPB, RR - base);
    const int T    = (nblk + TILE - 1) / TILE;

    // Packed weight pairs: w2[j] = (W[k][2j][lane], W[k][2j+1][lane])
    uint64_t w2[CIN / 2];
    {
        const float* wk = weight + (size_t)k * CIN * COUT;
        #pragma unroll
        for (int j = 0; j < CIN / 2; j++)
            w2[j] = pack2(__ldg(wk + (2 * j) * COUT + lane),
                          __ldg(wk + (2 * j + 1) * COUT + lane));
    }

    // Preload this block's rule indices (int4; TPB/4 = 128)
    if (tid < TPB / 4) {
        const int4* rin4  = reinterpret_cast<const int4*>(rules_in  + k * RR + base);
        const int4* rout4 = reinterpret_cast<const int4*>(rules_out + k * RR + base);
        if (tid * 4 < nblk) {
            reinterpret_cast<int4*>(sRin)[tid]  = __ldg(rin4  + tid);
            reinterpret_cast<int4*>(sRout)[tid] = __ldg(rout4 + tid);
        }
    }
    __syncthreads();

    // Async gather of one tile: 128 rows x 128 B = 1024 x 16B, 4 per thread
    auto issue_gather = [&](int t, int buf) {
        const int trules = min(TILE, nblk - t * TILE);
        #pragma unroll
        for (int i = 0; i < 4; i++) {
            int chunk = tid + i * 256;
            int row   = chunk >> 3;
            int seg   = chunk & 7;
            if (row < trules) {
                const float* g = feats + (size_t)sRin[t * TILE + row] * CIN + seg * 4;
                uint32_t s = (uint32_t)__cvta_generic_to_shared(&sIn[buf][row][seg * 4]);
                asm volatile("cp.async.cg.shared.global [%0], [%1], 16;\n"
                             :: "r"(s), "l"(g));
            }
        }
    };

    issue_gather(0, 0);
    asm volatile("cp.async.commit_group;\n" ::: "memory");

    for (int t = 0; t < T; t++) {
        if (t + 1 < T) issue_gather(t + 1, (t + 1) & 1);
        asm volatile("cp.async.commit_group;\n" ::: "memory");
        asm volatile("cp.async.wait_group 1;\n" ::: "memory");
        __syncthreads();

        const int trules = min(TILE, nblk - t * TILE);
        const int buf = t & 1;

        // ---- compute: warp owns rules [warp*16, warp*16+16); lane = channel
        #pragma unroll 1
        for (int i = 0; i < RPW; i++) {
            int row = warp * RPW + i;
            if (row < trules) {
                const ulonglong2* inr =
                    reinterpret_cast<const ulonglong2*>(sIn[buf][row]);
                uint64_t a0 = 0, a1 = 0, a2 = 0, a3 = 0;
                #pragma unroll
                for (int j = 0; j < 4; j++) {
                    ulonglong2 qa = inr[j];        // floats 4j .. 4j+3
                    ulonglong2 qb = inr[j + 4];    // floats 16+4j .. 16+4j+3
                    fma2(a0, qa.x, w2[2 * j]);
                    fma2(a1, qa.y, w2[2 * j + 1]);
                    fma2(a2, qb.x, w2[2 * j + 8]);
                    fma2(a3, qb.y, w2[2 * j + 9]);
                }
                sAcc[row][lane] = unpack_sum(add2(add2(a0, a1), add2(a2, a3)));
            }
        }
        __syncwarp();

        // ---- flush: transpose via smem, one v4 RED per 4 channels
        // 16 rules x 8 segs = 128 tasks / 32 lanes = 4 iterations
        #pragma unroll
        for (int i = 0; i < 4; i++) {
            int task = i * 32 + lane;
            int rloc = task >> 3;            // 0..15
            int seg  = task & 7;             // 0..7
            int row  = warp * RPW + rloc;
            if (row < trules) {
                const float* ap = &sAcc[row][seg * 4];
                float v0 = ap[0], v1 = ap[1], v2 = ap[2], v3 = ap[3];
                int ro = sRout[t * TILE + row];
                red4(out + (size_t)ro * COUT + seg * 4, v0, v1, v2, v3);
            }
        }
        __syncthreads();   // protect sIn[buf] before gather(t+2) overwrites it
    }
}

// ---------------------------------------------------------------------------
extern "C" void kernel_launch(void* const* d_in, const int* in_sizes, int n_in,
                              void* d_out, int out_size) {
    const float* feats  = (const float*)d_in[0];
    const float* weight = (const float*)d_in[1];
    const float* bias   = (const float*)d_in[2];
    const int*   rin    = (const int*)  d_in[3];
    const int*   rout   = (const int*)  d_in[4];
    float* out = (float*)d_out;

    const int total4 = NOUT * COUT / 4;
    init_out_kernel<<<(total4 + 255) / 256, 256>>>(out, bias);

    dim3 grid((RR + TPB - 1) / TPB, KK);
    scatter_conv_kernel<<<grid, 256>>>(feats, weight, rin, rout, out);
}

// round 8
// speedup vs baseline: 2.0995x; 1.6249x over previous
#include <cuda_runtime.h>
#include <cstdint>

// Problem constants
#define KK    8
#define RR    200000
#define CIN   32
#define COUT  32
#define NOUT  400000
#define TPB   512        // rules per block
#define NTHR  128        // 4 warps
#define WARPS 4
#define RPW   16         // rules per warp-tile
#define TILE  (WARPS * RPW)   // 64 rules per block iteration

// smem layout (bytes)
#define AROW    80                  // A row pitch (16B-mult, ldmatrix conflict-free)
#define A_PLANE (16 * AROW)         // 1280 (one bf16 plane, 16 rows)
#define A_WARP  (2 * A_PLANE)       // 2560 (hi + lo planes)
#define OFF_A   0                   // 4 warps -> 10240
#define TROWF   36                  // transpose row pitch in floats (144B)
#define T_WARP  (16 * TROWF * 4)    // 2304
#define OFF_T   10240               // 4 warps -> 9216, end 19456
#define OFF_RIN  19456              // 512 ints
#define OFF_ROUT 21504              // 512 ints
#define SMEM_BYTES 23552

// ---------------------------------------------------------------------------
// helpers
// ---------------------------------------------------------------------------
__device__ __forceinline__ uint32_t smem_u32(const void* p) {
    uint32_t a;
    asm("{ .reg .u64 t; cvta.to.shared.u64 t, %1; cvt.u32.u64 %0, t; }" : "=r"(a) : "l"(p));
    return a;
}
__device__ __forceinline__ uint32_t cvt_bf16x2(float hi, float lo) {  // (hi<<16)|lo
    uint32_t r;
    asm("cvt.rn.bf16x2.f32 %0, %1, %2;" : "=r"(r) : "f"(hi), "f"(lo));
    return r;
}
__device__ __forceinline__ void sts64(uint32_t a, uint32_t x, uint32_t y) {
    asm volatile("st.shared.v2.b32 [%0], {%1,%2};" :: "r"(a), "r"(x), "r"(y));
}
__device__ __forceinline__ void red4(float* addr, float a, float b, float c, float d) {
    asm volatile("red.global.add.v4.f32 [%0], {%1,%2,%3,%4};"
                 :: "l"(addr), "f"(a), "f"(b), "f"(c), "f"(d) : "memory");
}
__device__ __forceinline__ void ldmx4(uint32_t* r, uint32_t addr) {
    asm volatile("ldmatrix.sync.aligned.m8n8.x4.shared.b16 {%0,%1,%2,%3}, [%4];"
                 : "=r"(r[0]), "=r"(r[1]), "=r"(r[2]), "=r"(r[3]) : "r"(addr));
}
__device__ __forceinline__ void mma_bf16(float* d, const uint32_t* a, const uint32_t* b) {
    asm volatile("mma.sync.aligned.m16n8k16.row.col.f32.bf16.bf16.f32 "
                 "{%0,%1,%2,%3}, {%4,%5,%6,%7}, {%8,%9}, {%0,%1,%2,%3};"
                 : "+f"(d[0]), "+f"(d[1]), "+f"(d[2]), "+f"(d[3])
                 : "r"(a[0]), "r"(a[1]), "r"(a[2]), "r"(a[3]), "r"(b[0]), "r"(b[1]));
}

// ---------------------------------------------------------------------------
// Kernel 1: initialize output to bias
// ---------------------------------------------------------------------------
__global__ void init_out_kernel(float* __restrict__ out,
                                const float* __restrict__ bias) {
    int idx = blockIdx.x * blockDim.x + threadIdx.x;
    const int total4 = NOUT * COUT / 4;
    if (idx < total4) {
        int c = (idx & 7) * 4;
        float4 v = make_float4(bias[c], bias[c + 1], bias[c + 2], bias[c + 3]);
        reinterpret_cast<float4*>(out)[idx] = v;
    }
}

// ---------------------------------------------------------------------------
// Kernel 2: gather -> bf16 hi/lo split -> mma.sync (HMMA) -> coalesced RED
//   Warp-local pipelines; 16 rules per warp-tile; 24 mma per tile.
// ---------------------------------------------------------------------------
__global__ void __launch_bounds__(NTHR)
mma_scatter_kernel(const float* __restrict__ feats,
                   const float* __restrict__ weight,
                   const int*   __restrict__ rules_in,
                   const int*   __restrict__ rules_out,
                   float*       __restrict__ out)
{
    __shared__ __align__(128) char smem[SMEM_BYTES];
    const uint32_t sb = smem_u32(smem);
    const int tid  = threadIdx.x;
    const int lane = tid & 31;
    const int wid  = tid >> 5;
    const int g    = lane >> 2;       // mma group row
    const int t    = lane & 3;        // mma thread-in-group
    const int k    = blockIdx.y;
    const int base = blockIdx.x * TPB;
    const int nblk = min(TPB, RR - base);
    const int nit  = nblk / TILE;     // problem sizes make this exact

    int* sRin  = (int*)(smem + OFF_RIN);
    int* sRout = (int*)(smem + OFF_ROUT);

    // Stage rule indices (one int4 per thread covers TPB=512)
    {
        const int4* rin4  = (const int4*)(rules_in  + k * RR + base);
        const int4* rout4 = (const int4*)(rules_out + k * RR + base);
        if (tid * 4 < nblk) {
            ((int4*)sRin)[tid]  = __ldg(rin4  + tid);
            ((int4*)sRout)[tid] = __ldg(rout4 + tid);
        }
    }

    // Weight fragments (hi/lo split), B col-major for m16n8k16:
    //   reg0 = (B[k0+1][o]<<16)|B[k0][o], reg1 = (B[k0+9][o]<<16)|B[k0+8][o]
    //   k0 = kc*16 + 2t, o = n*8 + g
    uint32_t WH[4][2][2], WL[4][2][2];
    {
        const float* wk = weight + (size_t)k * CIN * COUT;
        #pragma unroll
        for (int n = 0; n < 4; n++)
            #pragma unroll
            for (int kc = 0; kc < 2; kc++) {
                int o  = n * 8 + g;
                int k0 = kc * 16 + 2 * t;
                float w00 = __ldg(wk + (k0 + 0) * COUT + o);
                float w01 = __ldg(wk + (k0 + 1) * COUT + o);
                float w10 = __ldg(wk + (k0 + 8) * COUT + o);
                float w11 = __ldg(wk + (k0 + 9) * COUT + o);
                uint32_t h0 = cvt_bf16x2(w01, w00);
                uint32_t h1 = cvt_bf16x2(w11, w10);
                WH[n][kc][0] = h0;
                WH[n][kc][1] = h1;
                float r00 = w00 - __uint_as_float(h0 << 16);
                float r01 = w01 - __uint_as_float(h0 & 0xFFFF0000u);
                float r10 = w10 - __uint_as_float(h1 << 16);
                float r11 = w11 - __uint_as_float(h1 & 0xFFFF0000u);
                WL[n][kc][0] = cvt_bf16x2(r01, r00);
                WL[n][kc][1] = cvt_bf16x2(r11, r10);
            }
    }
    __syncthreads();   // indices staged

    const uint32_t sAw = sb + OFF_A + wid * A_WARP;
    const uint32_t sTw = sb + OFF_T + wid * T_WARP;
    float* sTwp = (float*)(smem + OFF_T + wid * T_WARP);

    // ldmatrix lane address (invariant part): 4 tiles of 8x8
    //   lanes 0-7: rows 0-7 cols 0-7 | 8-15: rows 8-15 | 16-23: rows 0-7 cols 8-15 | 24-31: rows 8-15 cols 8-15
    const int lm_row = (lane & 7) + ((lane >> 3) & 1) * 8;
    const int lm_col = (lane >> 4) * 16;                 // byte offset within row half
    const uint32_t lm_base = sAw + lm_row * AROW + lm_col;

    // Per-lane gather slots: row = i*4 + (lane>>3), seg = lane&7
    const int g_row = lane >> 3;
    const int g_seg = lane & 7;

    float4 gbuf[4];
    auto do_gather = [&](int it) {
        #pragma unroll
        for (int i = 0; i < 4; i++) {
            int r = sRin[it * TILE + wid * RPW + i * 4 + g_row];
            gbuf[i] = __ldg((const float4*)(feats + (size_t)r * CIN) + g_seg);
        }
    };
    do_gather(0);

    for (int it = 0; it < nit; it++) {
        // ---- convert gathered f32 -> bf16 hi/lo planes in smem
        #pragma unroll
        for (int i = 0; i < 4; i++) {
            int row = i * 4 + g_row;
            float4 v = gbuf[i];
            uint32_t h0 = cvt_bf16x2(v.y, v.x);
            uint32_t h1 = cvt_bf16x2(v.w, v.z);
            float hx = __uint_as_float(h0 << 16);
            float hy = __uint_as_float(h0 & 0xFFFF0000u);
            float hz = __uint_as_float(h1 << 16);
            float hw = __uint_as_float(h1 & 0xFFFF0000u);
            uint32_t l0 = cvt_bf16x2(v.y - hy, v.x - hx);
            uint32_t l1 = cvt_bf16x2(v.w - hw, v.z - hz);
            sts64(sAw + row * AROW + g_seg * 8,           h0, h1);
            sts64(sAw + A_PLANE + row * AROW + g_seg * 8, l0, l1);
        }
        if (it + 1 < nit) do_gather(it + 1);   // overlap LDG with mma/epilogue
        __syncwarp();

        // ---- load A fragments (hi and lo planes, 2 K-chunks each)
        uint32_t ah[2][4], al[2][4];
        ldmx4(ah[0], lm_base);
        ldmx4(ah[1], lm_base + 32);
        ldmx4(al[0], lm_base + A_PLANE);
        ldmx4(al[1], lm_base + A_PLANE + 32);

        // ---- 24 mma: D[n] = sum_kc Ah*Wh + Al*Wh + Ah*Wl
        float D[4][4] = {};
        #pragma unroll
        for (int n = 0; n < 4; n++)
            #pragma unroll
            for (int kc = 0; kc < 2; kc++) {
                mma_bf16(D[n], ah[kc], WH[n][kc]);
                mma_bf16(D[n], al[kc], WH[n][kc]);
                mma_bf16(D[n], ah[kc], WL[n][kc]);
            }

        // ---- epilogue: fragments -> smem transpose -> coalesced v4 RED
        // D[n][0,1] = rule g,   cols n*8+2t, +1
        // D[n][2,3] = rule g+8, cols n*8+2t, +1
        #pragma unroll
        for (int n = 0; n < 4; n++) {
            int col = n * 8 + 2 * t;
            sts64(sTw + (g * TROWF + col) * 4,
                  __float_as_uint(D[n][0]), __float_as_uint(D[n][1]));
            sts64(sTw + ((g + 8) * TROWF + col) * 4,
                  __float_as_uint(D[n][2]), __float_as_uint(D[n][3]));
        }
        __syncwarp();

        #pragma unroll
        for (int i = 0; i < 4; i++) {
            int task = i * 32 + lane;
            int rl   = task >> 3;            // 0..15
            int seg  = task & 7;             // 0..7
            float4 v = *(const float4*)(sTwp + rl * TROWF + seg * 4);
            int ro = sRout[it * TILE + wid * RPW + rl];
            red4(out + (size_t)ro * COUT + seg * 4, v.x, v.y, v.z, v.w);
        }
        __syncwarp();   // sT reuse gate for next iteration
    }
}

// ---------------------------------------------------------------------------
extern "C" void kernel_launch(void* const* d_in, const int* in_sizes, int n_in,
                              void* d_out, int out_size) {
    const float* feats  = (const float*)d_in[0];
    const float* weight = (const float*)d_in[1];
    const float* bias   = (const float*)d_in[2];
    const int*   rin    = (const int*)  d_in[3];
    const int*   rout   = (const int*)  d_in[4];
    float* out = (float*)d_out;

    const int total4 = NOUT * COUT / 4;
    init_out_kernel<<<(total4 + 255) / 256, 256>>>(out, bias);

    dim3 grid((RR + TPB - 1) / TPB, KK);
    mma_scatter_kernel<<<grid, NTHR>>>(feats, weight, rin, rout, out);
}